// round 1
// baseline (speedup 1.0000x reference)
#include <cuda_runtime.h>
#include <cuda_bf16.h>
#include <math.h>

// Problem dims (fixed by the dataset)
#define NROWS 8192
#define H     256
#define K     64

// Q kernel tiling
#define RPB   16     // rows per block
#define TPB   256    // threads per block: 16 rows x 16 cluster-groups (4 clusters each)

// dynamic smem: cT[H][K] + zs[RPB][H]
#define SMEM_B ((H * K + RPB * H) * (int)sizeof(float))

__device__ float g_colsum[K];

__global__ void zero_colsum_kernel() {
    if (threadIdx.x < K) g_colsum[threadIdx.x] = 0.0f;
}

// Kernel 1: distances -> Q (row-normalized), accumulate column sums of Q.
__global__ void __launch_bounds__(TPB) q_kernel(const float* __restrict__ z,
                                                const float* __restrict__ cent,
                                                float* __restrict__ Q) {
    extern __shared__ float smem[];
    float* cT = smem;              // [H][K] : cT[h*K + k]
    float* zs = smem + H * K;      // [RPB][H]
    __shared__ float cnorm[K];
    __shared__ float csum[K];

    const int t = threadIdx.x;

    // Load centroids transposed into shared (coalesced float4 global reads).
    const float4* c4 = (const float4*)cent;
    for (int idx = t; idx < (K * H) / 4; idx += TPB) {
        int lin = idx * 4;
        int k = lin >> 8;          // / H
        int h = lin & (H - 1);     // % H
        float4 v = c4[idx];
        cT[(h + 0) * K + k] = v.x;
        cT[(h + 1) * K + k] = v.y;
        cT[(h + 2) * K + k] = v.z;
        cT[(h + 3) * K + k] = v.w;
    }

    // Load the z row tile.
    const float4* z4 = (const float4*)(z + (size_t)blockIdx.x * RPB * H);
    float4* zs4 = (float4*)zs;
    for (int idx = t; idx < (RPB * H) / 4; idx += TPB) zs4[idx] = z4[idx];

    if (t < K) csum[t] = 0.0f;
    __syncthreads();

    // Centroid squared norms.
    if (t < K) {
        float s = 0.0f;
        #pragma unroll 8
        for (int h = 0; h < H; ++h) {
            float v = cT[h * K + t];
            s = fmaf(v, v, s);
        }
        cnorm[t] = s;
    }
    __syncthreads();

    const int r = t >> 4;          // row within tile  (0..15)
    const int g = t & 15;          // cluster group -> clusters 4g..4g+3
    const float* zrow = zs + r * H;
    const float* cbase = cT + 4 * g;

    float acc0 = 0.f, acc1 = 0.f, acc2 = 0.f, acc3 = 0.f, zz = 0.f;

    #pragma unroll 4
    for (int h = 0; h < H; h += 4) {
        float4 zv = *(const float4*)(zrow + h);
        zz = fmaf(zv.x, zv.x, zz);
        zz = fmaf(zv.y, zv.y, zz);
        zz = fmaf(zv.z, zv.z, zz);
        zz = fmaf(zv.w, zv.w, zz);

        float4 c0 = *(const float4*)(cbase + (h + 0) * K);
        acc0 = fmaf(zv.x, c0.x, acc0);
        acc1 = fmaf(zv.x, c0.y, acc1);
        acc2 = fmaf(zv.x, c0.z, acc2);
        acc3 = fmaf(zv.x, c0.w, acc3);

        float4 c1 = *(const float4*)(cbase + (h + 1) * K);
        acc0 = fmaf(zv.y, c1.x, acc0);
        acc1 = fmaf(zv.y, c1.y, acc1);
        acc2 = fmaf(zv.y, c1.z, acc2);
        acc3 = fmaf(zv.y, c1.w, acc3);

        float4 c2 = *(const float4*)(cbase + (h + 2) * K);
        acc0 = fmaf(zv.z, c2.x, acc0);
        acc1 = fmaf(zv.z, c2.y, acc1);
        acc2 = fmaf(zv.z, c2.z, acc2);
        acc3 = fmaf(zv.z, c2.w, acc3);

        float4 c3 = *(const float4*)(cbase + (h + 3) * K);
        acc0 = fmaf(zv.w, c3.x, acc0);
        acc1 = fmaf(zv.w, c3.y, acc1);
        acc2 = fmaf(zv.w, c3.z, acc2);
        acc3 = fmaf(zv.w, c3.w, acc3);
    }

    // s = ||z||^2 + ||c||^2 - 2 z.c  (clamped), q_un = 1/(1+sqrt(s))
    float s0 = fmaxf(fmaf(-2.f, acc0, zz + cnorm[4 * g + 0]), 0.f);
    float s1 = fmaxf(fmaf(-2.f, acc1, zz + cnorm[4 * g + 1]), 0.f);
    float s2 = fmaxf(fmaf(-2.f, acc2, zz + cnorm[4 * g + 2]), 0.f);
    float s3 = fmaxf(fmaf(-2.f, acc3, zz + cnorm[4 * g + 3]), 0.f);

    float q0 = 1.0f / (1.0f + sqrtf(s0));
    float q1 = 1.0f / (1.0f + sqrtf(s1));
    float q2 = 1.0f / (1.0f + sqrtf(s2));
    float q3 = 1.0f / (1.0f + sqrtf(s3));

    // Row-sum across the 16 lanes sharing this row (xor masks 8..1 stay in 16-lane halves).
    float lsum = (q0 + q1) + (q2 + q3);
    #pragma unroll
    for (int m = 8; m; m >>= 1) lsum += __shfl_xor_sync(0xffffffffu, lsum, m);
    float inv = 1.0f / lsum;
    q0 *= inv; q1 *= inv; q2 *= inv; q3 *= inv;

    // Store Q (float4, coalesced: one row = 256B written by 16 lanes)
    const int row = blockIdx.x * RPB + r;
    float4 qv = make_float4(q0, q1, q2, q3);
    *(float4*)(Q + (size_t)row * K + 4 * g) = qv;

    // Block-level column-sum accumulation, then one global atomic per column.
    atomicAdd(&csum[4 * g + 0], q0);
    atomicAdd(&csum[4 * g + 1], q1);
    atomicAdd(&csum[4 * g + 2], q2);
    atomicAdd(&csum[4 * g + 3], q3);
    __syncthreads();
    if (t < K) atomicAdd(&g_colsum[t], csum[t]);
}

// Kernel 2: P = rownorm( Q^2 / colsum(Q) ). One warp per row, 2 columns per lane.
__global__ void __launch_bounds__(256) p_kernel(const float* __restrict__ Q,
                                                float* __restrict__ P) {
    const int lane = threadIdx.x & 31;
    const int warp = threadIdx.x >> 5;
    const int row = blockIdx.x * 8 + warp;

    float2 q = ((const float2*)(Q + (size_t)row * K))[lane];
    float inv0 = 1.0f / g_colsum[2 * lane + 0];
    float inv1 = 1.0f / g_colsum[2 * lane + 1];
    float p0 = q.x * q.x * inv0;
    float p1 = q.y * q.y * inv1;

    float s = p0 + p1;
    #pragma unroll
    for (int m = 16; m; m >>= 1) s += __shfl_xor_sync(0xffffffffu, s, m);
    float inv = 1.0f / s;

    float2 pv = make_float2(p0 * inv, p1 * inv);
    ((float2*)(P + (size_t)row * K))[lane] = pv;
}

extern "C" void kernel_launch(void* const* d_in, const int* in_sizes, int n_in,
                              void* d_out, int out_size) {
    const float* z    = (const float*)d_in[0];   // (8192, 256) f32
    const float* cent = (const float*)d_in[1];   // (64, 256)   f32
    float* Q = (float*)d_out;                    // first 8192*64 floats
    float* P = Q + (size_t)NROWS * K;            // next  8192*64 floats

    cudaFuncSetAttribute(q_kernel, cudaFuncAttributeMaxDynamicSharedMemorySize, SMEM_B);

    zero_colsum_kernel<<<1, K>>>();
    q_kernel<<<NROWS / RPB, TPB, SMEM_B>>>(z, cent, Q);
    p_kernel<<<NROWS / 8, 256>>>(Q, P);
}

// round 2
// speedup vs baseline: 2.8667x; 2.8667x over previous
#include <cuda_runtime.h>
#include <cuda_bf16.h>
#include <math.h>

#define NROWS 8192
#define H     256
#define K     64

#define RPB   32     // rows per block (2 rows per thread)
#define TPB   256    // 16 row-pairs x 16 cluster-groups

// dynamic smem: cT[H][K] + zs[RPB][H]
#define SMEM_B ((H * K + RPB * H) * (int)sizeof(float))

__device__ float g_cT[H * K];     // centroids transposed: cT[h*K + k]
__device__ float g_cnorm[K];
__device__ float g_colsum[K];

// Prep: transpose centroids (coalesced writes), centroid norms, zero colsums.
// 64 blocks x 256 threads. Block b owns cnorm[b]; all blocks do transpose slices.
__global__ void __launch_bounds__(256) prep_kernel(const float* __restrict__ cent) {
    const int b = blockIdx.x;      // 0..63
    const int t = threadIdx.x;     // 0..255

    // Transpose element: tid -> (h, k); read scattered, write coalesced.
    const int tid = b * 256 + t;
    const int k = tid & (K - 1);
    const int h = tid >> 6;
    g_cT[h * K + k] = cent[k * H + h];

    // cnorm[b] = sum_h cent[b][h]^2  (block reduction)
    float v = cent[b * H + t];
    float s = v * v;
    #pragma unroll
    for (int m = 16; m; m >>= 1) s += __shfl_xor_sync(0xffffffffu, s, m);
    __shared__ float ws[8];
    if ((t & 31) == 0) ws[t >> 5] = s;
    __syncthreads();
    if (t == 0) {
        float tot = 0.f;
        #pragma unroll
        for (int i = 0; i < 8; i++) tot += ws[i];
        g_cnorm[b] = tot;
        g_colsum[b] = 0.f;
    }
}

// Q kernel: distances -> Q (row-normalized) + column-sum accumulation.
// Each thread: 2 rows x 4 clusters.
__global__ void __launch_bounds__(TPB) q_kernel(const float* __restrict__ z,
                                                float* __restrict__ Q) {
    extern __shared__ float smem[];
    float* cT = smem;              // [H][K]
    float* zs = smem + H * K;      // [RPB][H]
    __shared__ float cnormS[K];
    __shared__ float csum[K];
    __shared__ float znorm[RPB];

    const int t = threadIdx.x;

    // Linear, conflict-free smem fills.
    {
        const float4* src = (const float4*)g_cT;
        float4* dst = (float4*)cT;
        #pragma unroll
        for (int i = 0; i < (H * K) / (4 * TPB); i++)
            dst[t + i * TPB] = src[t + i * TPB];
    }
    {
        const float4* src = (const float4*)(z + (size_t)blockIdx.x * RPB * H);
        float4* dst = (float4*)zs;
        #pragma unroll
        for (int i = 0; i < (RPB * H) / (4 * TPB); i++)
            dst[t + i * TPB] = src[t + i * TPB];
    }
    if (t < K) { cnormS[t] = g_cnorm[t]; csum[t] = 0.f; }
    __syncthreads();

    // Per-row ||z||^2: 8 lanes per row, 8 float4 each.
    {
        const int row8 = t >> 3;       // 0..31
        const int lane8 = t & 7;
        const float4* zr4 = (const float4*)zs + row8 * (H / 4);
        float s = 0.f;
        #pragma unroll
        for (int j = 0; j < 8; j++) {
            float4 v = zr4[lane8 + j * 8];
            s = fmaf(v.x, v.x, s);
            s = fmaf(v.y, v.y, s);
            s = fmaf(v.z, v.z, s);
            s = fmaf(v.w, v.w, s);
        }
        #pragma unroll
        for (int m = 4; m; m >>= 1) s += __shfl_xor_sync(0xffffffffu, s, m);
        if (lane8 == 0) znorm[row8] = s;
    }
    __syncthreads();

    const int r = t >> 4;              // row pair 0..15 -> rows 2r, 2r+1
    const int g = t & 15;              // clusters 4g..4g+3
    const float* zA = zs + (2 * r) * H;
    const float* zB = zs + (2 * r + 1) * H;
    const float* cb = cT + 4 * g;

    float a00 = 0.f, a01 = 0.f, a02 = 0.f, a03 = 0.f;
    float a10 = 0.f, a11 = 0.f, a12 = 0.f, a13 = 0.f;

    #pragma unroll 4
    for (int h = 0; h < H; h += 4) {
        float4 va = *(const float4*)(zA + h);
        float4 vb = *(const float4*)(zB + h);

        float4 c0 = *(const float4*)(cb + (h + 0) * K);
        a00 = fmaf(va.x, c0.x, a00); a01 = fmaf(va.x, c0.y, a01);
        a02 = fmaf(va.x, c0.z, a02); a03 = fmaf(va.x, c0.w, a03);
        a10 = fmaf(vb.x, c0.x, a10); a11 = fmaf(vb.x, c0.y, a11);
        a12 = fmaf(vb.x, c0.z, a12); a13 = fmaf(vb.x, c0.w, a13);

        float4 c1 = *(const float4*)(cb + (h + 1) * K);
        a00 = fmaf(va.y, c1.x, a00); a01 = fmaf(va.y, c1.y, a01);
        a02 = fmaf(va.y, c1.z, a02); a03 = fmaf(va.y, c1.w, a03);
        a10 = fmaf(vb.y, c1.x, a10); a11 = fmaf(vb.y, c1.y, a11);
        a12 = fmaf(vb.y, c1.z, a12); a13 = fmaf(vb.y, c1.w, a13);

        float4 c2 = *(const float4*)(cb + (h + 2) * K);
        a00 = fmaf(va.z, c2.x, a00); a01 = fmaf(va.z, c2.y, a01);
        a02 = fmaf(va.z, c2.z, a02); a03 = fmaf(va.z, c2.w, a03);
        a10 = fmaf(vb.z, c2.x, a10); a11 = fmaf(vb.z, c2.y, a11);
        a12 = fmaf(vb.z, c2.z, a12); a13 = fmaf(vb.z, c2.w, a13);

        float4 c3 = *(const float4*)(cb + (h + 3) * K);
        a00 = fmaf(va.w, c3.x, a00); a01 = fmaf(va.w, c3.y, a01);
        a02 = fmaf(va.w, c3.z, a02); a03 = fmaf(va.w, c3.w, a03);
        a10 = fmaf(vb.w, c3.x, a10); a11 = fmaf(vb.w, c3.y, a11);
        a12 = fmaf(vb.w, c3.z, a12); a13 = fmaf(vb.w, c3.w, a13);
    }

    const float znA = znorm[2 * r];
    const float znB = znorm[2 * r + 1];
    const float cn0 = cnormS[4 * g + 0], cn1 = cnormS[4 * g + 1];
    const float cn2 = cnormS[4 * g + 2], cn3 = cnormS[4 * g + 3];

    float q00 = 1.f / (1.f + sqrtf(fmaxf(fmaf(-2.f, a00, znA + cn0), 0.f)));
    float q01 = 1.f / (1.f + sqrtf(fmaxf(fmaf(-2.f, a01, znA + cn1), 0.f)));
    float q02 = 1.f / (1.f + sqrtf(fmaxf(fmaf(-2.f, a02, znA + cn2), 0.f)));
    float q03 = 1.f / (1.f + sqrtf(fmaxf(fmaf(-2.f, a03, znA + cn3), 0.f)));
    float q10 = 1.f / (1.f + sqrtf(fmaxf(fmaf(-2.f, a10, znB + cn0), 0.f)));
    float q11 = 1.f / (1.f + sqrtf(fmaxf(fmaf(-2.f, a11, znB + cn1), 0.f)));
    float q12 = 1.f / (1.f + sqrtf(fmaxf(fmaf(-2.f, a12, znB + cn2), 0.f)));
    float q13 = 1.f / (1.f + sqrtf(fmaxf(fmaf(-2.f, a13, znB + cn3), 0.f)));

    // Row sums across the 16 lanes sharing each row (xor 8..1 stays in-group).
    float sA = (q00 + q01) + (q02 + q03);
    float sB = (q10 + q11) + (q12 + q13);
    #pragma unroll
    for (int m = 8; m; m >>= 1) {
        sA += __shfl_xor_sync(0xffffffffu, sA, m);
        sB += __shfl_xor_sync(0xffffffffu, sB, m);
    }
    float invA = 1.f / sA, invB = 1.f / sB;
    q00 *= invA; q01 *= invA; q02 *= invA; q03 *= invA;
    q10 *= invB; q11 *= invB; q12 *= invB; q13 *= invB;

    const int row = blockIdx.x * RPB + 2 * r;
    *(float4*)(Q + (size_t)row * K + 4 * g)       = make_float4(q00, q01, q02, q03);
    *(float4*)(Q + (size_t)(row + 1) * K + 4 * g) = make_float4(q10, q11, q12, q13);

    // Column sums: block-level smem accumulation, then one global atomic/col.
    atomicAdd(&csum[4 * g + 0], q00 + q10);
    atomicAdd(&csum[4 * g + 1], q01 + q11);
    atomicAdd(&csum[4 * g + 2], q02 + q12);
    atomicAdd(&csum[4 * g + 3], q03 + q13);
    __syncthreads();
    if (t < K) atomicAdd(&g_colsum[t], csum[t]);
}

// P = rownorm( Q^2 / colsum(Q) ). One warp per row, 2 columns per lane.
__global__ void __launch_bounds__(256) p_kernel(const float* __restrict__ Q,
                                                float* __restrict__ P) {
    const int lane = threadIdx.x & 31;
    const int warp = threadIdx.x >> 5;
    const int row = blockIdx.x * 8 + warp;

    float2 q = ((const float2*)(Q + (size_t)row * K))[lane];
    float inv0 = 1.0f / g_colsum[2 * lane + 0];
    float inv1 = 1.0f / g_colsum[2 * lane + 1];
    float p0 = q.x * q.x * inv0;
    float p1 = q.y * q.y * inv1;

    float s = p0 + p1;
    #pragma unroll
    for (int m = 16; m; m >>= 1) s += __shfl_xor_sync(0xffffffffu, s, m);
    float inv = 1.0f / s;

    ((float2*)(P + (size_t)row * K))[lane] = make_float2(p0 * inv, p1 * inv);
}

extern "C" void kernel_launch(void* const* d_in, const int* in_sizes, int n_in,
                              void* d_out, int out_size) {
    const float* z    = (const float*)d_in[0];   // (8192, 256) f32
    const float* cent = (const float*)d_in[1];   // (64, 256)   f32
    float* Q = (float*)d_out;
    float* P = Q + (size_t)NROWS * K;

    cudaFuncSetAttribute(q_kernel, cudaFuncAttributeMaxDynamicSharedMemorySize, SMEM_B);

    prep_kernel<<<K, 256>>>(cent);
    q_kernel<<<NROWS / RPB, TPB, SMEM_B>>>(z, Q);
    p_kernel<<<NROWS / 8, 256>>>(Q, P);
}

// round 3
// speedup vs baseline: 2.8707x; 1.0014x over previous
#include <cuda_runtime.h>
#include <cuda_bf16.h>
#include <math.h>

#define NROWS 8192
#define H     256
#define K     64

#define RPB   32     // rows per block (2 rows per thread)
#define TPB   256    // 16 row-pairs x 16 cluster-groups
#define NBLK  (NROWS / RPB)   // 256

// dynamic smem: cT[H][K] + zs[RPB][H]
#define SMEM_B ((H * K + RPB * H) * (int)sizeof(float))

__device__ float g_cT[H * K];     // centroids transposed: cT[h*K + k]
__device__ float g_cnorm[K];
__device__ float g_colsum[K];
__device__ unsigned int g_arrive; // grid-sync counter (reset by prep each replay)

__device__ __forceinline__ unsigned long long pack2(float lo, float hi) {
    unsigned long long r;
    asm("mov.b64 %0, {%1, %2};" : "=l"(r) : "f"(lo), "f"(hi));
    return r;
}
__device__ __forceinline__ unsigned long long fma2(unsigned long long a,
                                                   unsigned long long b,
                                                   unsigned long long c) {
    unsigned long long d;
    asm("fma.rn.f32x2 %0, %1, %2, %3;" : "=l"(d) : "l"(a), "l"(b), "l"(c));
    return d;
}
__device__ __forceinline__ void unpack2(unsigned long long v, float& lo, float& hi) {
    asm("mov.b64 {%0, %1}, %2;" : "=f"(lo), "=f"(hi) : "l"(v));
}

// Prep: transpose centroids, centroid norms, zero colsums + sync counter.
__global__ void __launch_bounds__(256) prep_kernel(const float* __restrict__ cent) {
    const int b = blockIdx.x;      // 0..63
    const int t = threadIdx.x;     // 0..255

    const int tid = b * 256 + t;
    const int k = tid & (K - 1);
    const int h = tid >> 6;
    g_cT[h * K + k] = cent[k * H + h];

    float v = cent[b * H + t];
    float s = v * v;
    #pragma unroll
    for (int m = 16; m; m >>= 1) s += __shfl_xor_sync(0xffffffffu, s, m);
    __shared__ float ws[8];
    if ((t & 31) == 0) ws[t >> 5] = s;
    __syncthreads();
    if (t == 0) {
        float tot = 0.f;
        #pragma unroll
        for (int i = 0; i < 8; i++) tot += ws[i];
        g_cnorm[b] = tot;
        g_colsum[b] = 0.f;
        if (b == 0) g_arrive = 0u;
    }
}

// Fused kernel: distances -> Q (row-normalized), colsum accumulation,
// grid sync via atomic counter, then P from in-register Q.
__global__ void __launch_bounds__(TPB) qp_kernel(const float* __restrict__ z,
                                                 float* __restrict__ Q,
                                                 float* __restrict__ P) {
    extern __shared__ float smem[];
    float* cT = smem;              // [H][K]
    float* zs = smem + H * K;      // [RPB][H]
    __shared__ float cnormS[K];
    __shared__ float csum[K];
    __shared__ float znorm[RPB];

    const int t = threadIdx.x;

    // Linear, conflict-free smem fills.
    {
        const float4* src = (const float4*)g_cT;
        float4* dst = (float4*)cT;
        #pragma unroll
        for (int i = 0; i < (H * K) / (4 * TPB); i++)
            dst[t + i * TPB] = src[t + i * TPB];
    }
    {
        const float4* src = (const float4*)(z + (size_t)blockIdx.x * RPB * H);
        float4* dst = (float4*)zs;
        #pragma unroll
        for (int i = 0; i < (RPB * H) / (4 * TPB); i++)
            dst[t + i * TPB] = src[t + i * TPB];
    }
    if (t < K) { cnormS[t] = g_cnorm[t]; csum[t] = 0.f; }
    __syncthreads();

    // Per-row ||z||^2: 8 lanes per row.
    {
        const int row8 = t >> 3;
        const int lane8 = t & 7;
        const float4* zr4 = (const float4*)zs + row8 * (H / 4);
        float s = 0.f;
        #pragma unroll
        for (int j = 0; j < 8; j++) {
            float4 v = zr4[lane8 + j * 8];
            s = fmaf(v.x, v.x, s);
            s = fmaf(v.y, v.y, s);
            s = fmaf(v.z, v.z, s);
            s = fmaf(v.w, v.w, s);
        }
        #pragma unroll
        for (int m = 4; m; m >>= 1) s += __shfl_xor_sync(0xffffffffu, s, m);
        if (lane8 == 0) znorm[row8] = s;
    }
    __syncthreads();

    const int r = t >> 4;              // row pair -> rows 2r, 2r+1
    const int g = t & 15;              // clusters 4g..4g+3
    const float* zA = zs + (2 * r) * H;
    const float* zB = zs + (2 * r + 1) * H;
    const float* cb = cT + 4 * g;

    // Packed accumulators: (k, k+1) pairs per row.
    unsigned long long aA01 = 0ull, aA23 = 0ull, aB01 = 0ull, aB23 = 0ull;

    #pragma unroll 4
    for (int h = 0; h < H; h += 4) {
        float4 va = *(const float4*)(zA + h);
        float4 vb = *(const float4*)(zB + h);

        {
            ulonglong2 c = *(const ulonglong2*)(cb + (h + 0) * K);
            unsigned long long za = pack2(va.x, va.x), zb = pack2(vb.x, vb.x);
            aA01 = fma2(za, c.x, aA01); aA23 = fma2(za, c.y, aA23);
            aB01 = fma2(zb, c.x, aB01); aB23 = fma2(zb, c.y, aB23);
        }
        {
            ulonglong2 c = *(const ulonglong2*)(cb + (h + 1) * K);
            unsigned long long za = pack2(va.y, va.y), zb = pack2(vb.y, vb.y);
            aA01 = fma2(za, c.x, aA01); aA23 = fma2(za, c.y, aA23);
            aB01 = fma2(zb, c.x, aB01); aB23 = fma2(zb, c.y, aB23);
        }
        {
            ulonglong2 c = *(const ulonglong2*)(cb + (h + 2) * K);
            unsigned long long za = pack2(va.z, va.z), zb = pack2(vb.z, vb.z);
            aA01 = fma2(za, c.x, aA01); aA23 = fma2(za, c.y, aA23);
            aB01 = fma2(zb, c.x, aB01); aB23 = fma2(zb, c.y, aB23);
        }
        {
            ulonglong2 c = *(const ulonglong2*)(cb + (h + 3) * K);
            unsigned long long za = pack2(va.w, va.w), zb = pack2(vb.w, vb.w);
            aA01 = fma2(za, c.x, aA01); aA23 = fma2(za, c.y, aA23);
            aB01 = fma2(zb, c.x, aB01); aB23 = fma2(zb, c.y, aB23);
        }
    }

    float a00, a01, a02, a03, a10, a11, a12, a13;
    unpack2(aA01, a00, a01); unpack2(aA23, a02, a03);
    unpack2(aB01, a10, a11); unpack2(aB23, a12, a13);

    const float znA = znorm[2 * r];
    const float znB = znorm[2 * r + 1];
    const float cn0 = cnormS[4 * g + 0], cn1 = cnormS[4 * g + 1];
    const float cn2 = cnormS[4 * g + 2], cn3 = cnormS[4 * g + 3];

    float q00 = 1.f / (1.f + sqrtf(fmaxf(fmaf(-2.f, a00, znA + cn0), 0.f)));
    float q01 = 1.f / (1.f + sqrtf(fmaxf(fmaf(-2.f, a01, znA + cn1), 0.f)));
    float q02 = 1.f / (1.f + sqrtf(fmaxf(fmaf(-2.f, a02, znA + cn2), 0.f)));
    float q03 = 1.f / (1.f + sqrtf(fmaxf(fmaf(-2.f, a03, znA + cn3), 0.f)));
    float q10 = 1.f / (1.f + sqrtf(fmaxf(fmaf(-2.f, a10, znB + cn0), 0.f)));
    float q11 = 1.f / (1.f + sqrtf(fmaxf(fmaf(-2.f, a11, znB + cn1), 0.f)));
    float q12 = 1.f / (1.f + sqrtf(fmaxf(fmaf(-2.f, a12, znB + cn2), 0.f)));
    float q13 = 1.f / (1.f + sqrtf(fmaxf(fmaf(-2.f, a13, znB + cn3), 0.f)));

    // Row normalization (16-lane groups).
    float sA = (q00 + q01) + (q02 + q03);
    float sB = (q10 + q11) + (q12 + q13);
    #pragma unroll
    for (int m = 8; m; m >>= 1) {
        sA += __shfl_xor_sync(0xffffffffu, sA, m);
        sB += __shfl_xor_sync(0xffffffffu, sB, m);
    }
    float invA = 1.f / sA, invB = 1.f / sB;
    q00 *= invA; q01 *= invA; q02 *= invA; q03 *= invA;
    q10 *= invB; q11 *= invB; q12 *= invB; q13 *= invB;

    const int row = blockIdx.x * RPB + 2 * r;
    *(float4*)(Q + (size_t)row * K + 4 * g)       = make_float4(q00, q01, q02, q03);
    *(float4*)(Q + (size_t)(row + 1) * K + 4 * g) = make_float4(q10, q11, q12, q13);

    // Column sums: smem accumulation -> one global atomic per column.
    atomicAdd(&csum[4 * g + 0], q00 + q10);
    atomicAdd(&csum[4 * g + 1], q01 + q11);
    atomicAdd(&csum[4 * g + 2], q02 + q12);
    atomicAdd(&csum[4 * g + 3], q03 + q13);
    __syncthreads();
    if (t < K) atomicAdd(&g_colsum[t], csum[t]);

    // ---- Grid sync: all 256 blocks resident (2/SM x 148 SMs), spin is safe ----
    __threadfence();
    __syncthreads();
    if (t == 0) {
        atomicAdd(&g_arrive, 1u);
        while (true) {
            unsigned int v;
            asm volatile("ld.global.acquire.gpu.u32 %0, [%1];"
                         : "=r"(v) : "l"(&g_arrive));
            if (v >= (unsigned)NBLK) break;
        }
    }
    __syncthreads();

    // ---- P from in-register Q ----
    if (t < K) csum[t] = __ldcg(&g_colsum[t]);   // final colsums, L2 read
    __syncthreads();

    float i0 = 1.f / csum[4 * g + 0], i1 = 1.f / csum[4 * g + 1];
    float i2 = 1.f / csum[4 * g + 2], i3 = 1.f / csum[4 * g + 3];

    float p00 = q00 * q00 * i0, p01 = q01 * q01 * i1;
    float p02 = q02 * q02 * i2, p03 = q03 * q03 * i3;
    float p10 = q10 * q10 * i0, p11 = q11 * q11 * i1;
    float p12 = q12 * q12 * i2, p13 = q13 * q13 * i3;

    float tA = (p00 + p01) + (p02 + p03);
    float tB = (p10 + p11) + (p12 + p13);
    #pragma unroll
    for (int m = 8; m; m >>= 1) {
        tA += __shfl_xor_sync(0xffffffffu, tA, m);
        tB += __shfl_xor_sync(0xffffffffu, tB, m);
    }
    float ivA = 1.f / tA, ivB = 1.f / tB;

    *(float4*)(P + (size_t)row * K + 4 * g)       = make_float4(p00 * ivA, p01 * ivA, p02 * ivA, p03 * ivA);
    *(float4*)(P + (size_t)(row + 1) * K + 4 * g) = make_float4(p10 * ivB, p11 * ivB, p12 * ivB, p13 * ivB);
}

extern "C" void kernel_launch(void* const* d_in, const int* in_sizes, int n_in,
                              void* d_out, int out_size) {
    const float* z    = (const float*)d_in[0];   // (8192, 256) f32
    const float* cent = (const float*)d_in[1];   // (64, 256)   f32
    float* Q = (float*)d_out;
    float* P = Q + (size_t)NROWS * K;

    cudaFuncSetAttribute(qp_kernel, cudaFuncAttributeMaxDynamicSharedMemorySize, SMEM_B);

    prep_kernel<<<K, 256>>>(cent);
    qp_kernel<<<NBLK, TPB, SMEM_B>>>(z, Q, P);
}

// round 4
// speedup vs baseline: 4.4579x; 1.5529x over previous
#include <cuda_runtime.h>
#include <cuda_bf16.h>
#include <math.h>

#define NR   8192     // rows of z
#define HD   256      // feature dim
#define NC   64       // clusters
#define RPB  64       // rows per block
#define TPB  512      // threads per block (16 warps: 4 warp_m x 4 warp_n)
#define NBLK (NR / RPB)   // 128 blocks -> one wave, 1 block/SM

// dynamic smem tiles, each [64][256] bf16 = 32KB, row stride 512B, XOR-swizzled
#define OFF_ZH 0
#define OFF_ZL 32768
#define OFF_CH 65536
#define OFF_CL 98304
#define SMEM_B 131072

__device__ float g_part[NBLK * NC];   // per-block partial column sums
__device__ unsigned int g_arrive;     // epoch ticket counter (static zero-init)

#define LDSM4(r, addr) \
    asm volatile("ldmatrix.sync.aligned.m8n8.x4.shared.b16 {%0,%1,%2,%3}, [%4];" \
        : "=r"((r)[0]), "=r"((r)[1]), "=r"((r)[2]), "=r"((r)[3]) : "r"(addr))

#define MMA16816(d, a, b0, b1) \
    asm volatile("mma.sync.aligned.m16n8k16.row.col.f32.bf16.bf16.f32 " \
        "{%0,%1,%2,%3},{%4,%5,%6,%7},{%8,%9},{%0,%1,%2,%3};" \
        : "+f"((d)[0]), "+f"((d)[1]), "+f"((d)[2]), "+f"((d)[3]) \
        : "r"((a)[0]), "r"((a)[1]), "r"((a)[2]), "r"((a)[3]), "r"(b0), "r"(b1))

__device__ __forceinline__ unsigned bf2_bits(__nv_bfloat162 h) {
    return *reinterpret_cast<unsigned*>(&h);
}

// Convert one fp32 row tile into hi/lo bf16 swizzled smem + accumulate norm.
// 8 lanes per row, 8 float4 per lane.
__device__ __forceinline__ void convert_rows(const float4* __restrict__ g4,
                                             char* hi, char* lo,
                                             float* norm_out, int t) {
    const int row = t >> 3;
    const int l8 = t & 7;
    float acc = 0.f;
    #pragma unroll
    for (int j = 0; j < 8; j++) {
        const int c4 = l8 + 8 * j;                 // float4 index, k0 = 4*c4
        float4 v = g4[row * (HD / 4) + c4];
        acc = fmaf(v.x, v.x, acc);
        acc = fmaf(v.y, v.y, acc);
        acc = fmaf(v.z, v.z, acc);
        acc = fmaf(v.w, v.w, acc);

        __nv_bfloat162 h01 = __floats2bfloat162_rn(v.x, v.y);
        __nv_bfloat162 h23 = __floats2bfloat162_rn(v.z, v.w);
        float lx = v.x - __low2float(h01);
        float ly = v.y - __high2float(h01);
        float lz = v.z - __low2float(h23);
        float lw = v.w - __high2float(h23);
        __nv_bfloat162 l01 = __floats2bfloat162_rn(lx, ly);
        __nv_bfloat162 l23 = __floats2bfloat162_rn(lz, lw);

        const int byteoff = 8 * c4;                // bf16 bytes: k0*2
        const int chunk = byteoff >> 4;
        const int inner = byteoff & 15;            // 0 or 8
        const unsigned off = row * 512 + (((chunk ^ (row & 7)) << 4) | inner);
        *(uint2*)(hi + off) = make_uint2(bf2_bits(h01), bf2_bits(h23));
        *(uint2*)(lo + off) = make_uint2(bf2_bits(l01), bf2_bits(l23));
    }
    acc += __shfl_xor_sync(0xffffffffu, acc, 1);
    acc += __shfl_xor_sync(0xffffffffu, acc, 2);
    acc += __shfl_xor_sync(0xffffffffu, acc, 4);
    if (l8 == 0) norm_out[row] = acc;
}

__global__ void __launch_bounds__(TPB, 1)
fused_kernel(const float* __restrict__ z, const float* __restrict__ cent,
             float* __restrict__ Q, float* __restrict__ P) {
    extern __shared__ char smem[];
    char* zh = smem + OFF_ZH;
    char* zl = smem + OFF_ZL;
    char* ch = smem + OFF_CH;
    char* cl = smem + OFF_CL;
    __shared__ float s_zn[RPB], s_cn[NC];
    __shared__ float s_rs[RPB], s_cs[NC], s_ct[NC], s_pr[RPB];

    const int t = threadIdx.x;
    const unsigned sb = (unsigned)__cvta_generic_to_shared(smem);

    if (t < NC) { s_cs[t] = 0.f; s_ct[t] = 0.f; }
    if (t < RPB) { s_rs[t] = 0.f; s_pr[t] = 0.f; }

    // ---- Phase 1: load + split-convert z tile and full centroid matrix ----
    convert_rows((const float4*)(z + (size_t)blockIdx.x * RPB * HD), zh, zl, s_zn, t);
    convert_rows((const float4*)cent, ch, cl, s_cn, t);
    __syncthreads();

    // ---- Phase 2: GEMM mainloop (3-term split bf16 mma) ----
    const int lane = t & 31, wid = t >> 5;
    const int wm = wid >> 2, wn = wid & 3;
    const int tile = lane >> 3, rit = lane & 7;

    const int arow = wm * 16 + rit + 8 * (tile & 1);
    const int acb = tile >> 1;
    const unsigned azh = sb + OFF_ZH + arow * 512;
    const unsigned azl = sb + OFF_ZL + arow * 512;
    const int axor = arow & 7;

    const int brow = wn * 16 + rit + 8 * (tile >> 1);
    const int bcb = tile & 1;
    const unsigned bch = sb + OFF_CH + brow * 512;
    const unsigned bcl = sb + OFF_CL + brow * 512;
    const int bxor = brow & 7;

    float d0[4] = {0.f, 0.f, 0.f, 0.f};   // n-half 0
    float d1[4] = {0.f, 0.f, 0.f, 0.f};   // n-half 1

    #pragma unroll
    for (int ks = 0; ks < 16; ks++) {
        const unsigned aoff = (unsigned)(((2 * ks + acb) ^ axor) << 4);
        const unsigned boff = (unsigned)(((2 * ks + bcb) ^ bxor) << 4);
        unsigned ah[4], al[4], bhf[4], blf[4];
        LDSM4(ah, azh + aoff);
        LDSM4(bhf, bch + boff);
        LDSM4(al, azl + aoff);
        LDSM4(blf, bcl + boff);
        MMA16816(d0, ah, bhf[0], bhf[1]);
        MMA16816(d1, ah, bhf[2], bhf[3]);
        MMA16816(d0, ah, blf[0], blf[1]);
        MMA16816(d1, ah, blf[2], blf[3]);
        MMA16816(d0, al, bhf[0], bhf[1]);
        MMA16816(d1, al, bhf[2], bhf[3]);
    }

    // ---- Phase 3: epilogue -> Q ----
    const int gid = lane >> 2, tig = lane & 3;
    const int R0 = wm * 16 + gid, R1 = R0 + 8;
    const float znA = s_zn[R0], znB = s_zn[R1];
    const int c00 = wn * 16 + 2 * tig;       // n-half 0 cols: c00, c00+1
    const int c10 = c00 + 8;                 // n-half 1 cols
    const float cnA0 = s_cn[c00], cnA1 = s_cn[c00 + 1];
    const float cnB0 = s_cn[c10], cnB1 = s_cn[c10 + 1];

    float q00 = 1.f / (1.f + sqrtf(fmaxf(fmaf(-2.f, d0[0], znA + cnA0), 0.f)));
    float q01 = 1.f / (1.f + sqrtf(fmaxf(fmaf(-2.f, d0[1], znA + cnA1), 0.f)));
    float q02 = 1.f / (1.f + sqrtf(fmaxf(fmaf(-2.f, d0[2], znB + cnA0), 0.f)));
    float q03 = 1.f / (1.f + sqrtf(fmaxf(fmaf(-2.f, d0[3], znB + cnA1), 0.f)));
    float q10 = 1.f / (1.f + sqrtf(fmaxf(fmaf(-2.f, d1[0], znA + cnB0), 0.f)));
    float q11 = 1.f / (1.f + sqrtf(fmaxf(fmaf(-2.f, d1[1], znA + cnB1), 0.f)));
    float q12 = 1.f / (1.f + sqrtf(fmaxf(fmaf(-2.f, d1[2], znB + cnB0), 0.f)));
    float q13 = 1.f / (1.f + sqrtf(fmaxf(fmaf(-2.f, d1[3], znB + cnB1), 0.f)));

    // row sums (reduce over tig lanes, then cross-warp via smem atomics)
    float rs0 = (q00 + q01) + (q10 + q11);
    float rs1 = (q02 + q03) + (q12 + q13);
    rs0 += __shfl_xor_sync(0xffffffffu, rs0, 1);
    rs0 += __shfl_xor_sync(0xffffffffu, rs0, 2);
    rs1 += __shfl_xor_sync(0xffffffffu, rs1, 1);
    rs1 += __shfl_xor_sync(0xffffffffu, rs1, 2);
    if (tig == 0) { atomicAdd(&s_rs[R0], rs0); atomicAdd(&s_rs[R1], rs1); }
    __syncthreads();

    const float ir0 = 1.f / s_rs[R0], ir1 = 1.f / s_rs[R1];
    q00 *= ir0; q01 *= ir0; q10 *= ir0; q11 *= ir0;
    q02 *= ir1; q03 *= ir1; q12 *= ir1; q13 *= ir1;

    const int gA = blockIdx.x * RPB + R0;
    const int gB = blockIdx.x * RPB + R1;
    *(float2*)(Q + (size_t)gA * NC + c00) = make_float2(q00, q01);
    *(float2*)(Q + (size_t)gB * NC + c00) = make_float2(q02, q03);
    *(float2*)(Q + (size_t)gA * NC + c10) = make_float2(q10, q11);
    *(float2*)(Q + (size_t)gB * NC + c10) = make_float2(q12, q13);

    // column sums of normalized Q (reduce over gid lanes)
    float cA0 = q00 + q02, cA1 = q01 + q03;
    float cB0 = q10 + q12, cB1 = q11 + q13;
    #pragma unroll
    for (int m = 4; m <= 16; m <<= 1) {
        cA0 += __shfl_xor_sync(0xffffffffu, cA0, m);
        cA1 += __shfl_xor_sync(0xffffffffu, cA1, m);
        cB0 += __shfl_xor_sync(0xffffffffu, cB0, m);
        cB1 += __shfl_xor_sync(0xffffffffu, cB1, m);
    }
    if (lane < 4) {
        atomicAdd(&s_cs[c00], cA0);
        atomicAdd(&s_cs[c00 + 1], cA1);
        atomicAdd(&s_cs[c10], cB0);
        atomicAdd(&s_cs[c10 + 1], cB1);
    }
    __syncthreads();

    // publish block partial colsums
    if (t < NC) g_part[blockIdx.x * NC + t] = s_cs[t];
    __threadfence();
    __syncthreads();

    // ---- single-wave grid sync (epoch ticket; replay-deterministic) ----
    if (t == 0) {
        unsigned ticket;
        asm volatile("atom.global.add.release.gpu.u32 %0, [%1], 1;"
                     : "=r"(ticket) : "l"(&g_arrive) : "memory");
        const unsigned target = (ticket / NBLK + 1u) * NBLK;
        unsigned v;
        do {
            asm volatile("ld.global.acquire.gpu.u32 %0, [%1];"
                         : "=r"(v) : "l"(&g_arrive) : "memory");
        } while (v < target);
    }
    __syncthreads();
    __threadfence();

    // total column sums
    {
        const int col = t & 63, grp = t >> 6;   // 8 groups x 16 blocks
        float s = 0.f;
        #pragma unroll
        for (int b = 0; b < NBLK / 8; b++)
            s += __ldcg(&g_part[(grp * (NBLK / 8) + b) * NC + col]);
        atomicAdd(&s_ct[col], s);
    }
    __syncthreads();

    // ---- Phase 4: P from in-register Q ----
    const float icA0 = 1.f / s_ct[c00], icA1 = 1.f / s_ct[c00 + 1];
    const float icB0 = 1.f / s_ct[c10], icB1 = 1.f / s_ct[c10 + 1];

    float p00 = q00 * q00 * icA0, p01 = q01 * q01 * icA1;
    float p02 = q02 * q02 * icA0, p03 = q03 * q03 * icA1;
    float p10 = q10 * q10 * icB0, p11 = q11 * q11 * icB1;
    float p12 = q12 * q12 * icB0, p13 = q13 * q13 * icB1;

    float ps0 = (p00 + p01) + (p10 + p11);
    float ps1 = (p02 + p03) + (p12 + p13);
    ps0 += __shfl_xor_sync(0xffffffffu, ps0, 1);
    ps0 += __shfl_xor_sync(0xffffffffu, ps0, 2);
    ps1 += __shfl_xor_sync(0xffffffffu, ps1, 1);
    ps1 += __shfl_xor_sync(0xffffffffu, ps1, 2);
    if (tig == 0) { atomicAdd(&s_pr[R0], ps0); atomicAdd(&s_pr[R1], ps1); }
    __syncthreads();

    const float ip0 = 1.f / s_pr[R0], ip1 = 1.f / s_pr[R1];
    *(float2*)(P + (size_t)gA * NC + c00) = make_float2(p00 * ip0, p01 * ip0);
    *(float2*)(P + (size_t)gB * NC + c00) = make_float2(p02 * ip1, p03 * ip1);
    *(float2*)(P + (size_t)gA * NC + c10) = make_float2(p10 * ip0, p11 * ip0);
    *(float2*)(P + (size_t)gB * NC + c10) = make_float2(p12 * ip1, p13 * ip1);
}

extern "C" void kernel_launch(void* const* d_in, const int* in_sizes, int n_in,
                              void* d_out, int out_size) {
    const float* z    = (const float*)d_in[0];   // (8192, 256) f32
    const float* cent = (const float*)d_in[1];   // (64, 256)   f32
    float* Q = (float*)d_out;
    float* P = Q + (size_t)NR * NC;

    cudaFuncSetAttribute(fused_kernel, cudaFuncAttributeMaxDynamicSharedMemorySize, SMEM_B);
    fused_kernel<<<NBLK, TPB, SMEM_B>>>(z, cent, Q, P);
}